// round 1
// baseline (speedup 1.0000x reference)
#include <cuda_runtime.h>
#include <math.h>

// ---------------------------------------------------------------------------
// Problem constants
// ---------------------------------------------------------------------------
#define Bn   8
#define Cc   768
#define Sn   729            // 9*9*9
#define CS   (Cc * Sn)      // 559872
#define NHn  8
#define DH   96             // Cc / NHn
#define BSn  (Bn * Sn)      // 5832 tokens
#define HIDn 2048
#define En   3
#define C3   (3 * Cc)       // 2304
#define EH   (En * HIDn)    // 6144
#define EPSv 1e-5f

// ---------------------------------------------------------------------------
// Scratch (device globals; allocation-free per harness rules)
// ---------------------------------------------------------------------------
__device__ float g_tok   [BSn * Cc];            // tok (b,s,c); reused as proj-out
__device__ float g_qkv   [BSn * C3];            // qkv (b,s,3c)
__device__ float g_scores[64 * Sn * Sn];        // attention scores / probs (b*nh,s,s)
__device__ float g_attno [BSn * Cc];            // attn out (b,s,c); reused as moe-out
__device__ float g_tok2  [BSn * Cc];            // x2 tokens (b,s,c)
__device__ float g_wfull [BSn * En];            // routing weights
__device__ float g_gbuf  [BSn * EH];            // gate acts -> hid (in-place)
__device__ float g_ubuf  [BSn * EH];            // up acts
__device__ float g_part  [Bn * 64 * 2];         // LN partial sums
__device__ float g_stats [Bn * 2];              // LN final sum/sumsq

// ---------------------------------------------------------------------------
// LayerNorm: two-stage deterministic reduction + apply-with-transpose
// ---------------------------------------------------------------------------
__global__ void ln_reduce(const float* __restrict__ x) {
    int b = blockIdx.y;
    const float* xb = x + (size_t)b * CS;
    float s = 0.f, sq = 0.f;
    for (int i = blockIdx.x * blockDim.x + threadIdx.x; i < CS;
         i += gridDim.x * blockDim.x) {
        float v = xb[i];
        s += v; sq += v * v;
    }
    __shared__ float sh1[256], sh2[256];
    sh1[threadIdx.x] = s; sh2[threadIdx.x] = sq;
    __syncthreads();
    for (int o = 128; o > 0; o >>= 1) {
        if (threadIdx.x < o) {
            sh1[threadIdx.x] += sh1[threadIdx.x + o];
            sh2[threadIdx.x] += sh2[threadIdx.x + o];
        }
        __syncthreads();
    }
    if (threadIdx.x == 0) {
        g_part[(b * 64 + blockIdx.x) * 2 + 0] = sh1[0];
        g_part[(b * 64 + blockIdx.x) * 2 + 1] = sh2[0];
    }
}

__global__ void ln_finalize() {
    int b = blockIdx.x;
    if (threadIdx.x == 0) {
        float s = 0.f, sq = 0.f;
        for (int i = 0; i < 64; i++) {
            s  += g_part[(b * 64 + i) * 2 + 0];
            sq += g_part[(b * 64 + i) * 2 + 1];
        }
        g_stats[b * 2 + 0] = s;
        g_stats[b * 2 + 1] = sq;
    }
}

// Apply LN and transpose (b,c,s) -> tok (b,s,c)
__global__ void ln_apply_tr(const float* __restrict__ x,
                            const float* __restrict__ lw,
                            const float* __restrict__ lb) {
    __shared__ float tile[32][33];
    int b = blockIdx.z;
    float mean = g_stats[b * 2 + 0] * (1.f / CS);
    float var  = g_stats[b * 2 + 1] * (1.f / CS) - mean * mean;
    float inv  = rsqrtf(var + EPSv);
    int s0 = blockIdx.x * 32, c0 = blockIdx.y * 32;
    #pragma unroll
    for (int i = 0; i < 4; i++) {
        int cl = threadIdx.y + i * 8;
        int s = s0 + threadIdx.x, c = c0 + cl;
        if (s < Sn && c < Cc) {
            size_t idx = (size_t)c * Sn + s;
            float v = (x[(size_t)b * CS + idx] - mean) * inv * lw[idx] + lb[idx];
            tile[cl][threadIdx.x] = v;
        }
    }
    __syncthreads();
    #pragma unroll
    for (int i = 0; i < 4; i++) {
        int sl = threadIdx.y + i * 8;
        int s = s0 + sl, c = c0 + threadIdx.x;
        if (s < Sn && c < Cc)
            g_tok[((size_t)b * Sn + s) * Cc + c] = tile[threadIdx.x][sl];
    }
}

// ---------------------------------------------------------------------------
// Generic tiled fp32 GEMM: C = A(MxK) * B(KxN), optionally B given as (NxK)
// row-major (BT=true => C[m][n] = sum_k A[m][k]*B[n][k]).
// Batched via blockIdx.z with a 2-level stride decomposition:
//   off = (z / zdiv) * s1 + (z % zdiv) * s2
// ---------------------------------------------------------------------------
template <bool BT>
__global__ void __launch_bounds__(256)
gemm_kernel(const float* __restrict__ A, const float* __restrict__ B,
            float* __restrict__ C,
            int M, int N, int K, int lda, int ldb, int ldc,
            int zdiv,
            long long sA1, long long sA2,
            long long sB1, long long sB2,
            long long sC1, long long sC2) {
    int z = blockIdx.z;
    long long zq = z / zdiv, zr = z % zdiv;
    A += zq * sA1 + zr * sA2;
    B += zq * sB1 + zr * sB2;
    C += zq * sC1 + zr * sC2;

    __shared__ float As[16][132];
    __shared__ float Bs[16][132];

    int tid = threadIdx.x;
    int tx = tid & 15, ty = tid >> 4;
    int m0 = blockIdx.y * 128, n0 = blockIdx.x * 128;

    float acc[8][8];
    #pragma unroll
    for (int i = 0; i < 8; i++)
        #pragma unroll
        for (int j = 0; j < 8; j++) acc[i][j] = 0.f;

    for (int k0 = 0; k0 < K; k0 += 16) {
        #pragma unroll
        for (int i = 0; i < 8; i++) {
            int idx = tid + i * 256;
            int r = idx >> 4, c = idx & 15;
            int gm = m0 + r, gk = k0 + c;
            As[c][r] = (gm < M && gk < K) ? A[(size_t)gm * lda + gk] : 0.f;
        }
        #pragma unroll
        for (int i = 0; i < 8; i++) {
            int idx = tid + i * 256;
            if (!BT) {
                int kk = idx >> 7, nn = idx & 127;
                int gk = k0 + kk, gn = n0 + nn;
                Bs[kk][nn] = (gk < K && gn < N) ? B[(size_t)gk * ldb + gn] : 0.f;
            } else {
                int kk = idx & 15, nn = idx >> 4;
                int gk = k0 + kk, gn = n0 + nn;
                Bs[kk][nn] = (gk < K && gn < N) ? B[(size_t)gn * ldb + gk] : 0.f;
            }
        }
        __syncthreads();
        #pragma unroll
        for (int kk = 0; kk < 16; kk++) {
            float a[8], bv[8];
            #pragma unroll
            for (int i = 0; i < 8; i++) a[i] = As[kk][ty * 8 + i];
            #pragma unroll
            for (int j = 0; j < 8; j++) bv[j] = Bs[kk][tx * 8 + j];
            #pragma unroll
            for (int i = 0; i < 8; i++)
                #pragma unroll
                for (int j = 0; j < 8; j++)
                    acc[i][j] = fmaf(a[i], bv[j], acc[i][j]);
        }
        __syncthreads();
    }
    #pragma unroll
    for (int i = 0; i < 8; i++) {
        int gm = m0 + ty * 8 + i;
        if (gm >= M) continue;
        #pragma unroll
        for (int j = 0; j < 8; j++) {
            int gn = n0 + tx * 8 + j;
            if (gn < N) C[(size_t)gm * ldc + gn] = acc[i][j];
        }
    }
}

// ---------------------------------------------------------------------------
// Row softmax (in place) — one block per row
// ---------------------------------------------------------------------------
__global__ void softmax_rows(float* __restrict__ data, int n) {
    float* row = data + (size_t)blockIdx.x * n;
    __shared__ float sh[256];
    float m = -INFINITY;
    for (int i = threadIdx.x; i < n; i += blockDim.x) m = fmaxf(m, row[i]);
    sh[threadIdx.x] = m; __syncthreads();
    for (int o = 128; o > 0; o >>= 1) {
        if (threadIdx.x < o) sh[threadIdx.x] = fmaxf(sh[threadIdx.x], sh[threadIdx.x + o]);
        __syncthreads();
    }
    m = sh[0]; __syncthreads();
    float sum = 0.f;
    for (int i = threadIdx.x; i < n; i += blockDim.x) {
        float e = expf(row[i] - m);
        row[i] = e; sum += e;
    }
    sh[threadIdx.x] = sum; __syncthreads();
    for (int o = 128; o > 0; o >>= 1) {
        if (threadIdx.x < o) sh[threadIdx.x] += sh[threadIdx.x + o];
        __syncthreads();
    }
    float inv = 1.f / sh[0];
    for (int i = threadIdx.x; i < n; i += blockDim.x) row[i] *= inv;
}

// ---------------------------------------------------------------------------
// Residual + transpose after proj: out(b,c,s) = x + po; also tok2(b,s,c)
// po lives in g_tok
// ---------------------------------------------------------------------------
__global__ void addproj_tr(const float* __restrict__ x, float* __restrict__ out) {
    __shared__ float shx[32][33];
    __shared__ float shy[32][33];
    int b = blockIdx.z;
    int s0 = blockIdx.x * 32, c0 = blockIdx.y * 32;
    #pragma unroll
    for (int i = 0; i < 4; i++) {
        int cl = threadIdx.y + i * 8;
        int s = s0 + threadIdx.x, c = c0 + cl;
        if (s < Sn && c < Cc)
            shx[cl][threadIdx.x] = x[(size_t)b * CS + (size_t)c * Sn + s];
    }
    __syncthreads();
    #pragma unroll
    for (int i = 0; i < 4; i++) {
        int sl = threadIdx.y + i * 8;
        int s = s0 + sl, c = c0 + threadIdx.x;
        if (s < Sn && c < Cc) {
            size_t ti = ((size_t)b * Sn + s) * Cc + c;
            float v = shx[threadIdx.x][sl] + g_tok[ti];
            g_tok2[ti] = v;
            shy[threadIdx.x][sl] = v;
        }
    }
    __syncthreads();
    #pragma unroll
    for (int i = 0; i < 4; i++) {
        int cl = threadIdx.y + i * 8;
        int s = s0 + threadIdx.x, c = c0 + cl;
        if (s < Sn && c < Cc)
            out[(size_t)b * CS + (size_t)c * Sn + s] = shy[cl][threadIdx.x];
    }
}

// ---------------------------------------------------------------------------
// Router: one warp per token. probs = softmax(tok2 @ router_w); top-2 of 3
// = drop min, renormalize.
// ---------------------------------------------------------------------------
__global__ void router_kernel(const float* __restrict__ rw) {
    int t = blockIdx.x * 8 + (threadIdx.x >> 5);
    int lane = threadIdx.x & 31;
    if (t >= BSn) return;
    const float* tk = g_tok2 + (size_t)t * Cc;
    float s0 = 0.f, s1 = 0.f, s2 = 0.f;
    for (int c = lane; c < Cc; c += 32) {
        float v = tk[c];
        s0 += v * rw[c * 3 + 0];
        s1 += v * rw[c * 3 + 1];
        s2 += v * rw[c * 3 + 2];
    }
    for (int o = 16; o > 0; o >>= 1) {
        s0 += __shfl_down_sync(0xffffffffu, s0, o);
        s1 += __shfl_down_sync(0xffffffffu, s1, o);
        s2 += __shfl_down_sync(0xffffffffu, s2, o);
    }
    if (lane == 0) {
        float m = fmaxf(s0, fmaxf(s1, s2));
        float p0 = expf(s0 - m), p1 = expf(s1 - m), p2 = expf(s2 - m);
        float tot = p0 + p1 + p2;
        p0 /= tot; p1 /= tot; p2 /= tot;
        // argmin with ties broken toward the LAST index (matches jax top_k keeping
        // earlier-index ties among the kept two)
        int amin = 0; float pm = p0;
        if (p1 <= pm) { amin = 1; pm = p1; }
        if (p2 <= pm) { amin = 2; pm = p2; }
        float denom = (p0 + p1 + p2) - pm;
        g_wfull[t * 3 + 0] = (amin == 0) ? 0.f : p0 / denom;
        g_wfull[t * 3 + 1] = (amin == 1) ? 0.f : p1 / denom;
        g_wfull[t * 3 + 2] = (amin == 2) ? 0.f : p2 / denom;
    }
}

// ---------------------------------------------------------------------------
// hid = wfull * silu(g) * u, in place over g_gbuf
// ---------------------------------------------------------------------------
__global__ void silu_kernel() {
    size_t n = (size_t)BSn * EH;
    for (size_t i = (size_t)blockIdx.x * blockDim.x + threadIdx.x; i < n;
         i += (size_t)gridDim.x * blockDim.x) {
        float g = g_gbuf[i];
        float u = g_ubuf[i];
        size_t t = i / EH;
        int e = (int)((i % EH) >> 11);  // /2048
        float w = g_wfull[t * 3 + e];
        float sg = g / (1.f + expf(-g));
        g_gbuf[i] = w * sg * u;
    }
}

// ---------------------------------------------------------------------------
// Final residual with transpose: out(b,c,s) += mo(b,s,c)  (mo in g_attno)
// ---------------------------------------------------------------------------
__global__ void addmoe_tr(float* __restrict__ out) {
    __shared__ float sh[32][33];
    int b = blockIdx.z;
    int s0 = blockIdx.x * 32, c0 = blockIdx.y * 32;
    #pragma unroll
    for (int i = 0; i < 4; i++) {
        int sl = threadIdx.y + i * 8;
        int s = s0 + sl, c = c0 + threadIdx.x;
        if (s < Sn && c < Cc)
            sh[threadIdx.x][sl] = g_attno[((size_t)b * Sn + s) * Cc + c];
    }
    __syncthreads();
    #pragma unroll
    for (int i = 0; i < 4; i++) {
        int cl = threadIdx.y + i * 8;
        int s = s0 + threadIdx.x, c = c0 + cl;
        if (s < Sn && c < Cc) {
            size_t idx = (size_t)b * CS + (size_t)c * Sn + s;
            out[idx] += sh[cl][threadIdx.x];
        }
    }
}

// ---------------------------------------------------------------------------
// Host launcher
// ---------------------------------------------------------------------------
extern "C" void kernel_launch(void* const* d_in, const int* in_sizes, int n_in,
                              void* d_out, int out_size) {
    const float* x        = (const float*)d_in[0];
    const float* ln_w     = (const float*)d_in[1];
    const float* ln_b     = (const float*)d_in[2];
    const float* qkv_w    = (const float*)d_in[3];
    const float* proj_w   = (const float*)d_in[4];
    const float* router_w = (const float*)d_in[5];
    const float* gate_w   = (const float*)d_in[6];
    const float* up_w     = (const float*)d_in[7];
    const float* down_w   = (const float*)d_in[8];
    float* out = (float*)d_out;

    float *tokp, *qkvp, *scoresp, *attnop, *tok2p, *gp, *up;
    cudaGetSymbolAddress((void**)&tokp,    g_tok);
    cudaGetSymbolAddress((void**)&qkvp,    g_qkv);
    cudaGetSymbolAddress((void**)&scoresp, g_scores);
    cudaGetSymbolAddress((void**)&attnop,  g_attno);
    cudaGetSymbolAddress((void**)&tok2p,   g_tok2);
    cudaGetSymbolAddress((void**)&gp,      g_gbuf);
    cudaGetSymbolAddress((void**)&up,      g_ubuf);

    dim3 trGrid((Sn + 31) / 32, Cc / 32, Bn);   // 23 x 24 x 8
    dim3 trBlk(32, 8);

    // 1) LayerNorm stats + apply/transpose -> tok (b,s,c)
    ln_reduce<<<dim3(64, Bn), 256>>>(x);
    ln_finalize<<<Bn, 1>>>();
    ln_apply_tr<<<trGrid, trBlk>>>(x, ln_w, ln_b);

    // 2) QKV: (5832 x 768) @ (768 x 2304)
    gemm_kernel<false><<<dim3(18, 46, 1), 256>>>(
        tokp, qkv_w, qkvp, BSn, C3, Cc, Cc, C3, C3,
        1, 0, 0, 0, 0, 0, 0);

    // 3) scores = Q @ K^T per (b,h): 729x729x96 (NT)
    gemm_kernel<true><<<dim3(6, 6, 64), 256>>>(
        qkvp, qkvp + Cc, scoresp, Sn, Sn, DH, C3, C3, Sn,
        NHn,
        (long long)Sn * C3, DH,
        (long long)Sn * C3, DH,
        (long long)NHn * Sn * Sn, (long long)Sn * Sn);

    // 4) softmax over rows (NO 1/sqrt(dh) scaling in reference)
    softmax_rows<<<64 * Sn, 256>>>(scoresp, Sn);

    // 5) O = P @ V per (b,h): 729x96x729 (NN), write (b,s,c=h*96+d)
    gemm_kernel<false><<<dim3(1, 6, 64), 256>>>(
        scoresp, qkvp + 2 * Cc, attnop, Sn, DH, Sn, Sn, C3, Cc,
        NHn,
        (long long)NHn * Sn * Sn, (long long)Sn * Sn,
        (long long)Sn * C3, DH,
        (long long)Sn * Cc, DH);

    // 6) proj: (5832 x 768) @ (768 x 768) -> po (into g_tok)
    gemm_kernel<false><<<dim3(6, 46, 1), 256>>>(
        attnop, proj_w, tokp, BSn, Cc, Cc, Cc, Cc, Cc,
        1, 0, 0, 0, 0, 0, 0);

    // 7) x2 = x + po : write out (b,c,s) and tok2 (b,s,c)
    addproj_tr<<<trGrid, trBlk>>>(x, out);

    // 8) router weights
    router_kernel<<<Sn, 256>>>(router_w);

    // 9) gate/up GEMMs per expert: (5832 x 768) @ (768 x 2048) -> (5832 x 6144)
    gemm_kernel<false><<<dim3(16, 46, En), 256>>>(
        tok2p, gate_w, gp, BSn, HIDn, Cc, Cc, HIDn, EH,
        1, 0, 0, (long long)Cc * HIDn, 0, HIDn, 0);
    gemm_kernel<false><<<dim3(16, 46, En), 256>>>(
        tok2p, up_w, up, BSn, HIDn, Cc, Cc, HIDn, EH,
        1, 0, 0, (long long)Cc * HIDn, 0, HIDn, 0);

    // 10) hid = wfull * silu(g) * u (in place in g_gbuf)
    silu_kernel<<<4096, 256>>>();

    // 11) moe = hid (5832 x 6144) @ down_w (6144 x 768) -> mo (g_attno)
    gemm_kernel<false><<<dim3(6, 46, 1), 256>>>(
        gp, down_w, attnop, BSn, Cc, EH, EH, Cc, Cc,
        1, 0, 0, 0, 0, 0, 0);

    // 12) out += mo (transposed add)
    addmoe_tr<<<trGrid, trBlk>>>(out);

    (void)in_sizes; (void)n_in; (void)out_size;
}